// round 1
// baseline (speedup 1.0000x reference)
#include <cuda_runtime.h>
#include <math.h>

#define T_LEN 24
#define BATCH 16
#define NH    8
#define HDIM  512
#define EDIM  4096
#define TB    (T_LEN*BATCH)     /* 384  */
#define TM1   (T_LEN-1)         /* 23   */
#define ROWS2 (TM1*BATCH)       /* 368  */

// ---------------- scratch (static device globals; no allocation) ------------
__device__ float g_xt[TB*EDIM];              // 6 MB   xt[t*B+b, e]
__device__ float g_qkv[TB*3*EDIM];           // 18.9MB qkv rows
__device__ float g_wbar[TM1*BATCH*NH*T_LEN]; // query-averaged attention weights
__device__ float g_pctx[ROWS2*EDIM];         // pooled context (pre-Wo)
__device__ float g_pooled[ROWS2*EDIM];       // pooled @ Wo^T + bo

// ---------------- small helpers ---------------------------------------------
__device__ __forceinline__ float wsum(float v){
  #pragma unroll
  for (int o=16;o;o>>=1) v += __shfl_xor_sync(0xffffffffu, v, o);
  return v;
}
__device__ __forceinline__ float wmax(float v){
  #pragma unroll
  for (int o=16;o;o>>=1) v = fmaxf(v, __shfl_xor_sync(0xffffffffu, v, o));
  return v;
}

// ---------------- 1) transpose x -> xt  -------------------------------------
// xt[(t*16+b)*4096 + f*64+n] = x[((b*64+f)*24 + t)*64 + n]
__global__ void k_transpose(const float* __restrict__ x){
  int i = blockIdx.x*blockDim.x + threadIdx.x;
  if (i >= TB*EDIM) return;
  int n  = i & 63;
  int f  = (i >> 6) & 63;
  int b  = (i >> 12) & 15;
  int t  = i >> 16;
  g_xt[i] = x[(((size_t)(b*64 + f))*T_LEN + t)*64 + n];
}

// ---------------- generic NT SGEMM body: C = A(M,K) * B(N,K)^T + bias -------
template<int BM,int BN,int TM,int TN>
__device__ __forceinline__ void sgemm_body(const float* __restrict__ A,
                                           const float* __restrict__ B,
                                           const float* __restrict__ bias,
                                           float* __restrict__ C,
                                           int M, int N, int K){
  __shared__ float As[16][BM+4];
  __shared__ float Bs[16][BN+4];
  const int tid = threadIdx.x;
  const int bm = blockIdx.y*BM, bn = blockIdx.x*BN;
  const int TCOLS = BN/TN;                 // thread-columns
  const int tm = (tid / TCOLS) * TM;
  const int tn = (tid % TCOLS) * TN;
  float acc[TM][TN];
  #pragma unroll
  for (int i=0;i<TM;i++)
    #pragma unroll
    for (int j=0;j<TN;j++) acc[i][j] = 0.f;

  for (int kt = 0; kt < K; kt += 16){
    // load A tile (BM x 16) as float4 along K, store transposed
    #pragma unroll
    for (int v = tid; v < BM*4; v += 256){
      int r  = v >> 2;
      int kc = (v & 3) << 2;
      int gr = bm + r;
      float4 q = (gr < M) ? *(const float4*)(A + (size_t)gr*K + kt + kc)
                          : make_float4(0.f,0.f,0.f,0.f);
      As[kc+0][r]=q.x; As[kc+1][r]=q.y; As[kc+2][r]=q.z; As[kc+3][r]=q.w;
    }
    // load B tile (BN x 16)
    #pragma unroll
    for (int v = tid; v < BN*4; v += 256){
      int r  = v >> 2;
      int kc = (v & 3) << 2;
      float4 q = *(const float4*)(B + (size_t)(bn + r)*K + kt + kc);
      Bs[kc+0][r]=q.x; Bs[kc+1][r]=q.y; Bs[kc+2][r]=q.z; Bs[kc+3][r]=q.w;
    }
    __syncthreads();
    #pragma unroll
    for (int k=0;k<16;k++){
      float a[TM], bb[TN];
      #pragma unroll
      for (int i=0;i<TM;i++) a[i]  = As[k][tm+i];
      #pragma unroll
      for (int j=0;j<TN;j++) bb[j] = Bs[k][tn+j];
      #pragma unroll
      for (int i=0;i<TM;i++)
        #pragma unroll
        for (int j=0;j<TN;j++) acc[i][j] += a[i]*bb[j];
    }
    __syncthreads();
  }
  #pragma unroll
  for (int i=0;i<TM;i++){
    int gr = bm + tm + i;
    if (gr < M){
      #pragma unroll
      for (int j=0;j<TN;j++)
        C[(size_t)gr*N + bn + tn + j] = acc[i][j] + bias[bn + tn + j];
    }
  }
}

// qkv = xt @ Wqkv^T + bqkv     (384 x 12288, K=4096)
__global__ __launch_bounds__(256) void sgemm_qkv(const float* __restrict__ W,
                                                 const float* __restrict__ bias){
  sgemm_body<128,128,8,8>(g_xt, W, bias, g_qkv, TB, 3*EDIM, EDIM);
}
// pooled = pctx @ Wo^T + bo    (368 x 4096, K=4096)
__global__ __launch_bounds__(256) void sgemm_out(const float* __restrict__ W,
                                                 const float* __restrict__ bias){
  sgemm_body<128,64,8,4>(g_pctx, W, bias, g_pooled, ROWS2, EDIM, EDIM);
}

// ---------------- 2) scores + per-step softmax + query-average --------------
// one block per (b,h); computes base[q][k] = q.k/sqrt(HD) + tril, then for
// each step t: wbar[t,b,h,k] = (1/(t+1)) * sum_{q<=t} softmax_k<=t(base[q,:])[k]
__global__ __launch_bounds__(256) void k_attn(){
  const int b = blockIdx.x >> 3, h = blockIdx.x & 7;
  __shared__ float Ks[T_LEN][257];          // 256-wide d-chunk of K rows
  __shared__ float base[T_LEN][T_LEN+1];
  const int tid = threadIdx.x, warp = tid>>5, lane = tid&31;

  for (int i=tid;i<T_LEN*T_LEN;i+=256) base[i/T_LEN][i%T_LEN] = 0.f;
  __syncthreads();

  for (int c=0;c<2;c++){
    for (int i=tid;i<T_LEN*256;i+=256){
      int k=i>>8, d=i&255;
      Ks[k][d] = g_qkv[((size_t)(k*BATCH+b))*(3*EDIM) + EDIM + h*HDIM + c*256 + d];
    }
    __syncthreads();
    for (int q=warp; q<T_LEN; q+=8){
      const float* qp = &g_qkv[((size_t)(q*BATCH+b))*(3*EDIM) + h*HDIM + c*256];
      float qr[8];
      #pragma unroll
      for (int i=0;i<8;i++) qr[i] = qp[lane + 32*i];
      for (int k=0;k<T_LEN;k++){
        float s = 0.f;
        #pragma unroll
        for (int i=0;i<8;i++) s += qr[i]*Ks[k][lane + 32*i];
        s = wsum(s);
        if (lane==0) base[q][k] += s;
      }
    }
    __syncthreads();
  }
  for (int i=tid;i<T_LEN*T_LEN;i+=256){
    int q=i/T_LEN, k=i%T_LEN;
    base[q][k] = base[q][k]*0.04419417382415922f + ((k<=q)?1.f:0.f);
  }
  __syncthreads();

  for (int t=warp; t<TM1; t+=8){
    const int k = lane;                      // k index (valid < T_LEN)
    float acc = 0.f;
    for (int q=0; q<=t; q++){
      float bv = (k<=t) ? base[q][k] : -1e30f;
      float m  = wmax(bv);
      float e  = (k<=t) ? __expf(base[q][k]-m) : 0.f;
      float s  = wsum(e);
      acc += e / s;
    }
    if (k < T_LEN)
      g_wbar[(((t*BATCH)+b)*NH + h)*T_LEN + k] = acc / (float)(t+1);
  }
}

// ---------------- 3) pooled context: pctx[t,b,h,:] = sum_k wbar * v ---------
__global__ __launch_bounds__(128) void k_pctx(){
  const int t = blockIdx.x, b = blockIdx.y, h = blockIdx.z;
  __shared__ float w[T_LEN];
  const int tid = threadIdx.x;
  if (tid < T_LEN) w[tid] = (tid<=t) ? g_wbar[((t*BATCH+b)*NH+h)*T_LEN + tid] : 0.f;
  __syncthreads();
  float a0=0.f,a1=0.f,a2=0.f,a3=0.f;
  for (int k=0;k<=t;k++){
    const float* vp = &g_qkv[((size_t)(k*BATCH+b))*(3*EDIM) + 2*EDIM + h*HDIM];
    float wk = w[k];
    a0 += wk*vp[tid];       a1 += wk*vp[tid+128];
    a2 += wk*vp[tid+256];   a3 += wk*vp[tid+384];
  }
  float* o = &g_pctx[((size_t)(t*BATCH+b))*EDIM + h*HDIM];
  o[tid]=a0; o[tid+128]=a1; o[tid+256]=a2; o[tid+384]=a3;
}

// ---------------- 4) head FC: out[b,f,t+1,n] = relu(P[f*64+:]·Wfc[n,:]+bfc) -
__global__ __launch_bounds__(256) void k_head(const float* __restrict__ Wfc,
                                              const float* __restrict__ bfc,
                                              float* __restrict__ out){
  const int t = blockIdx.x, b = blockIdx.y;
  __shared__ float P[EDIM];        // 16 KB
  __shared__ float Wf[64][65];
  const int tid = threadIdx.x;
  for (int i=tid;i<EDIM;i+=256) P[i] = g_pooled[((size_t)(t*BATCH+b))*EDIM + i];
  for (int i=tid;i<4096;i+=256) Wf[i>>6][i&63] = Wfc[i];
  __syncthreads();
  #pragma unroll 4
  for (int u=0;u<16;u++){
    int idx = tid + 256*u;             // 0..4095
    int f = idx >> 6, n = idx & 63;
    float s = bfc[n];
    #pragma unroll
    for (int j=0;j<64;j++) s += P[f*64+j]*Wf[n][j];
    out[(((size_t)(b*64+f))*T_LEN + (t+1))*64 + n] = fmaxf(s, 0.f);
  }
}

// ---------------- 5) copy t=0 slice ------------------------------------------
__global__ void k_copy0(const float* __restrict__ x, float* __restrict__ out){
  int i = blockIdx.x*blockDim.x + threadIdx.x;
  if (i >= BATCH*64*64) return;
  int n = i & 63, bf = i >> 6;
  size_t a = (size_t)bf*(T_LEN*64) + n;    // t = 0
  out[a] = x[a];
}

// ---------------- launch ------------------------------------------------------
extern "C" void kernel_launch(void* const* d_in, const int* in_sizes, int n_in,
                              void* d_out, int out_size){
  const float* x    = (const float*)d_in[0];
  const float* Wqkv = (const float*)d_in[1];
  const float* bqkv = (const float*)d_in[2];
  const float* Wo   = (const float*)d_in[3];
  const float* bo   = (const float*)d_in[4];
  const float* Wfc  = (const float*)d_in[5];
  const float* bfc  = (const float*)d_in[6];
  float* out = (float*)d_out;

  k_transpose<<<(TB*EDIM + 255)/256, 256>>>(x);
  sgemm_qkv<<<dim3(3*EDIM/128, TB/128), 256>>>(Wqkv, bqkv);
  k_attn<<<BATCH*NH, 256>>>();
  k_pctx<<<dim3(TM1, BATCH, NH), 128>>>();
  sgemm_out<<<dim3(EDIM/64, (ROWS2 + 127)/128), 256>>>(Wo, bo);
  k_head<<<dim3(TM1, BATCH), 256>>>(Wfc, bfc, out);
  k_copy0<<<(BATCH*64*64 + 255)/256, 256>>>(x, out);
}

// round 7
// speedup vs baseline: 1.8276x; 1.8276x over previous
#include <cuda_runtime.h>
#include <cuda_bf16.h>
#include <math.h>
#include <cstdint>

#define T_LEN 24
#define BATCH 16
#define NH    8
#define HDIM  512
#define EDIM  4096
#define TB    (T_LEN*BATCH)     /* 384  */
#define TM1   (T_LEN-1)         /* 23   */
#define ROWS2 (TM1*BATCH)       /* 368  */
#define ROWS2P 384              /* padded to 3*128 */
#define GK    4096
#define KC    32
#define NCHUNK (GK/KC)          /* 128 */

// ---------------- scratch (static device globals; no allocation) ------------
__device__ float g_xt[TB*EDIM];
__device__ float g_qkv[TB*3*EDIM];
__device__ float g_wbar[TM1*BATCH*NH*T_LEN];
__device__ float g_pctx[ROWS2P*EDIM];          // rows 368..383 stay zero
__device__ float g_pooled[ROWS2*EDIM];

// ---------------- mma.sync wrapper ------------------------------------------
__device__ __forceinline__ void mma16816(float* c,
                                         uint32_t a0, uint32_t a1, uint32_t a2, uint32_t a3,
                                         uint32_t b0, uint32_t b1){
  asm volatile(
    "mma.sync.aligned.m16n8k16.row.col.f32.bf16.bf16.f32 "
    "{%0,%1,%2,%3}, {%4,%5,%6,%7}, {%8,%9}, {%0,%1,%2,%3};"
    : "+f"(c[0]), "+f"(c[1]), "+f"(c[2]), "+f"(c[3])
    : "r"(a0), "r"(a1), "r"(a2), "r"(a3), "r"(b0), "r"(b1));
}

// word-permutation within each 8-word (k16) block so that a thread's two frag
// words (kp=tg and kp=tg+4) are adjacent -> one ld.shared.v2
__device__ __forceinline__ int permp(int kp){
  int blk = kp >> 3, kb = kp & 7;
  return blk*8 + ((kb < 4) ? (2*kb) : (2*(kb-4) + 1));
}

__device__ __forceinline__ uint32_t pack_hi(float x, float y,
                                            float& rx, float& ry){
  __nv_bfloat16 hx = __float2bfloat16(x), hy = __float2bfloat16(y);
  rx = x - __bfloat162float(hx);
  ry = y - __bfloat162float(hy);
  return ((uint32_t)__bfloat16_as_ushort(hy) << 16) | __bfloat16_as_ushort(hx);
}
__device__ __forceinline__ uint32_t pack_lo(float rx, float ry){
  __nv_bfloat16 lx = __float2bfloat16(rx), ly = __float2bfloat16(ry);
  return ((uint32_t)__bfloat16_as_ushort(ly) << 16) | __bfloat16_as_ushort(lx);
}

// ---------------- bf16-split tensor-core GEMM body ---------------------------
// C(M,Nn) = A(M,4096) @ B(Nn,4096)^T + bias ; rows >= Mvalid not stored.
// M, Nn multiples of 128 in the padded scratch buffers.
__device__ __forceinline__ void gemm_body(const float* __restrict__ A,
                                          const float* __restrict__ B,
                                          const float* __restrict__ bias,
                                          float* __restrict__ C,
                                          int Nn, int Mvalid){
  __shared__ uint32_t SM[4][128][20];   // [Ahi,Alo,Bhi,Blo][row][perm words]
  const int tid  = threadIdx.x;
  const int warp = tid >> 5, lane = tid & 31;
  const int g = lane >> 2, tg = lane & 3;
  const int bm = blockIdx.y*128, bn = blockIdx.x*128;
  const int wm = warp >> 2, wn = warp & 3;      // 2 x 4 warps
  const int R0 = wm*64, N0 = wn*32;

  float acc[4][4][4];
  #pragma unroll
  for (int i=0;i<4;i++)
    #pragma unroll
    for (int j=0;j<4;j++)
      #pragma unroll
      for (int r=0;r<4;r++) acc[i][j][r] = 0.f;

  const int prow = tid >> 3;      // producer row (0..127? no: lin>>3 with u)
  const int pq   = tid & 7;       // float4 index component
  (void)prow; (void)pq;

  float4 ra[4], rb[4];

  // ---- load chunk 0 ----
  {
    const float* Ap = A + (size_t)bm*GK;
    const float* Bp = B + (size_t)bn*GK;
    #pragma unroll
    for (int u=0;u<4;u++){
      int lin = u*256 + tid, row = lin>>3, q = lin&7;
      ra[u] = *(const float4*)(Ap + (size_t)row*GK + q*4);
      rb[u] = *(const float4*)(Bp + (size_t)row*GK + q*4);
    }
    #pragma unroll
    for (int u=0;u<4;u++){
      int lin = u*256 + tid, row = lin>>3, q = lin&7;
      int p0 = permp(2*q), p1 = permp(2*q+1);
      float rx,ry,rz,rw;
      uint32_t ah0 = pack_hi(ra[u].x, ra[u].y, rx, ry);
      uint32_t ah1 = pack_hi(ra[u].z, ra[u].w, rz, rw);
      SM[0][row][p0]=ah0; SM[0][row][p1]=ah1;
      SM[1][row][p0]=pack_lo(rx,ry); SM[1][row][p1]=pack_lo(rz,rw);
      uint32_t bh0 = pack_hi(rb[u].x, rb[u].y, rx, ry);
      uint32_t bh1 = pack_hi(rb[u].z, rb[u].w, rz, rw);
      SM[2][row][p0]=bh0; SM[2][row][p1]=bh1;
      SM[3][row][p0]=pack_lo(rx,ry); SM[3][row][p1]=pack_lo(rz,rw);
    }
  }
  __syncthreads();

  for (int c = 0; c < NCHUNK; c++){
    // prefetch chunk c+1 into registers
    if (c+1 < NCHUNK){
      const float* Ap = A + (size_t)bm*GK + (c+1)*KC;
      const float* Bp = B + (size_t)bn*GK + (c+1)*KC;
      #pragma unroll
      for (int u=0;u<4;u++){
        int lin = u*256 + tid, row = lin>>3, q = lin&7;
        ra[u] = *(const float4*)(Ap + (size_t)row*GK + q*4);
        rb[u] = *(const float4*)(Bp + (size_t)row*GK + q*4);
      }
    }
    // compute chunk c
    #pragma unroll
    for (int s=0;s<2;s++){
      const int pb = s*8 + 2*tg;
      uint2 bh[4], bl[4];
      #pragma unroll
      for (int j=0;j<4;j++){
        int n = N0 + 8*j + g;
        bh[j] = *(const uint2*)&SM[2][n][pb];
        bl[j] = *(const uint2*)&SM[3][n][pb];
      }
      #pragma unroll
      for (int i=0;i<4;i++){
        int r0 = R0 + 16*i + g;
        uint2 ah0 = *(const uint2*)&SM[0][r0  ][pb];
        uint2 ah1 = *(const uint2*)&SM[0][r0+8][pb];
        uint2 al0 = *(const uint2*)&SM[1][r0  ][pb];
        uint2 al1 = *(const uint2*)&SM[1][r0+8][pb];
        #pragma unroll
        for (int j=0;j<4;j++){
          mma16816(acc[i][j], ah0.x, ah1.x, ah0.y, ah1.y, bh[j].x, bh[j].y);
          mma16816(acc[i][j], ah0.x, ah1.x, ah0.y, ah1.y, bl[j].x, bl[j].y);
          mma16816(acc[i][j], al0.x, al1.x, al0.y, al1.y, bh[j].x, bh[j].y);
        }
      }
    }
    __syncthreads();
    if (c+1 < NCHUNK){
      #pragma unroll
      for (int u=0;u<4;u++){
        int lin = u*256 + tid, row = lin>>3, q = lin&7;
        int p0 = permp(2*q), p1 = permp(2*q+1);
        float rx,ry,rz,rw;
        uint32_t ah0 = pack_hi(ra[u].x, ra[u].y, rx, ry);
        uint32_t ah1 = pack_hi(ra[u].z, ra[u].w, rz, rw);
        SM[0][row][p0]=ah0; SM[0][row][p1]=ah1;
        SM[1][row][p0]=pack_lo(rx,ry); SM[1][row][p1]=pack_lo(rz,rw);
        uint32_t bh0 = pack_hi(rb[u].x, rb[u].y, rx, ry);
        uint32_t bh1 = pack_hi(rb[u].z, rb[u].w, rz, rw);
        SM[2][row][p0]=bh0; SM[2][row][p1]=bh1;
        SM[3][row][p0]=pack_lo(rx,ry); SM[3][row][p1]=pack_lo(rz,rw);
      }
      __syncthreads();
    }
  }

  // ---- epilogue: bias + store ----
  #pragma unroll
  for (int i=0;i<4;i++){
    int row0 = bm + R0 + 16*i + g;
    int row1 = row0 + 8;
    #pragma unroll
    for (int j=0;j<4;j++){
      int col = bn + N0 + 8*j + 2*tg;
      float b0 = bias[col], b1 = bias[col+1];
      if (row0 < Mvalid){
        float2 o; o.x = acc[i][j][0] + b0; o.y = acc[i][j][1] + b1;
        *(float2*)&C[(size_t)row0*Nn + col] = o;
      }
      if (row1 < Mvalid){
        float2 o; o.x = acc[i][j][2] + b0; o.y = acc[i][j][3] + b1;
        *(float2*)&C[(size_t)row1*Nn + col] = o;
      }
    }
  }
}

__global__ __launch_bounds__(256,1) void gemm_qkv(const float* __restrict__ W,
                                                  const float* __restrict__ bias){
  gemm_body(g_xt, W, bias, g_qkv, 3*EDIM, TB);
}
__global__ __launch_bounds__(256,1) void gemm_out(const float* __restrict__ W,
                                                  const float* __restrict__ bias){
  gemm_body(g_pctx, W, bias, g_pooled, EDIM, ROWS2);
}

// ---------------- small helpers ---------------------------------------------
__device__ __forceinline__ float wsum(float v){
  #pragma unroll
  for (int o=16;o;o>>=1) v += __shfl_xor_sync(0xffffffffu, v, o);
  return v;
}
__device__ __forceinline__ float wmax(float v){
  #pragma unroll
  for (int o=16;o;o>>=1) v = fmaxf(v, __shfl_xor_sync(0xffffffffu, v, o));
  return v;
}

// ---------------- 1) transpose x -> xt  -------------------------------------
__global__ void k_transpose(const float* __restrict__ x){
  int i = blockIdx.x*blockDim.x + threadIdx.x;
  if (i >= TB*EDIM) return;
  int n  = i & 63;
  int f  = (i >> 6) & 63;
  int b  = (i >> 12) & 15;
  int t  = i >> 16;
  g_xt[i] = x[(((size_t)(b*64 + f))*T_LEN + t)*64 + n];
}

// ---------------- 2) scores + per-step softmax + query-average --------------
__global__ __launch_bounds__(256) void k_attn(){
  const int b = blockIdx.x >> 3, h = blockIdx.x & 7;
  __shared__ float Ks[T_LEN][257];
  __shared__ float base[T_LEN][T_LEN+1];
  const int tid = threadIdx.x, warp = tid>>5, lane = tid&31;

  for (int i=tid;i<T_LEN*T_LEN;i+=256) base[i/T_LEN][i%T_LEN] = 0.f;
  __syncthreads();

  for (int c=0;c<2;c++){
    for (int i=tid;i<T_LEN*256;i+=256){
      int k=i>>8, d=i&255;
      Ks[k][d] = g_qkv[((size_t)(k*BATCH+b))*(3*EDIM) + EDIM + h*HDIM + c*256 + d];
    }
    __syncthreads();
    for (int q=warp; q<T_LEN; q+=8){
      const float* qp = &g_qkv[((size_t)(q*BATCH+b))*(3*EDIM) + h*HDIM + c*256];
      float qr[8];
      #pragma unroll
      for (int i=0;i<8;i++) qr[i] = qp[lane + 32*i];
      for (int k=0;k<T_LEN;k++){
        float s = 0.f;
        #pragma unroll
        for (int i=0;i<8;i++) s += qr[i]*Ks[k][lane + 32*i];
        s = wsum(s);
        if (lane==0) base[q][k] += s;
      }
    }
    __syncthreads();
  }
  for (int i=tid;i<T_LEN*T_LEN;i+=256){
    int q=i/T_LEN, k=i%T_LEN;
    base[q][k] = base[q][k]*0.04419417382415922f + ((k<=q)?1.f:0.f);
  }
  __syncthreads();

  for (int t=warp; t<TM1; t+=8){
    const int k = lane;
    float acc = 0.f;
    for (int q=0; q<=t; q++){
      float bv = (k<=t) ? base[q][k] : -1e30f;
      float m  = wmax(bv);
      float e  = (k<=t) ? __expf(base[q][k]-m) : 0.f;
      float s  = wsum(e);
      acc += e / s;
    }
    if (k < T_LEN)
      g_wbar[(((t*BATCH)+b)*NH + h)*T_LEN + k] = acc / (float)(t+1);
  }
}

// ---------------- 3) pooled context ------------------------------------------
__global__ __launch_bounds__(128) void k_pctx(){
  const int t = blockIdx.x, b = blockIdx.y, h = blockIdx.z;
  __shared__ float w[T_LEN];
  const int tid = threadIdx.x;
  if (tid < T_LEN) w[tid] = (tid<=t) ? g_wbar[((t*BATCH+b)*NH+h)*T_LEN + tid] : 0.f;
  __syncthreads();
  float a0=0.f,a1=0.f,a2=0.f,a3=0.f;
  for (int k=0;k<=t;k++){
    const float* vp = &g_qkv[((size_t)(k*BATCH+b))*(3*EDIM) + 2*EDIM + h*HDIM];
    float wk = w[k];
    a0 += wk*vp[tid];       a1 += wk*vp[tid+128];
    a2 += wk*vp[tid+256];   a3 += wk*vp[tid+384];
  }
  float* o = &g_pctx[((size_t)(t*BATCH+b))*EDIM + h*HDIM];
  o[tid]=a0; o[tid+128]=a1; o[tid+256]=a2; o[tid+384]=a3;
}

// ---------------- 4) head FC -------------------------------------------------
__global__ __launch_bounds__(256) void k_head(const float* __restrict__ Wfc,
                                              const float* __restrict__ bfc,
                                              float* __restrict__ out){
  const int t = blockIdx.x, b = blockIdx.y;
  __shared__ float P[EDIM];
  __shared__ float Wf[64][65];
  const int tid = threadIdx.x;
  for (int i=tid;i<EDIM;i+=256) P[i] = g_pooled[((size_t)(t*BATCH+b))*EDIM + i];
  for (int i=tid;i<4096;i+=256) Wf[i>>6][i&63] = Wfc[i];
  __syncthreads();
  #pragma unroll 4
  for (int u=0;u<16;u++){
    int idx = tid + 256*u;
    int f = idx >> 6, n = idx & 63;
    float s = bfc[n];
    #pragma unroll
    for (int j=0;j<64;j++) s += P[f*64+j]*Wf[n][j];
    out[(((size_t)(b*64+f))*T_LEN + (t+1))*64 + n] = fmaxf(s, 0.f);
  }
}

// ---------------- 5) copy t=0 slice ------------------------------------------
__global__ void k_copy0(const float* __restrict__ x, float* __restrict__ out){
  int i = blockIdx.x*blockDim.x + threadIdx.x;
  if (i >= BATCH*64*64) return;
  int n = i & 63, bf = i >> 6;
  size_t a = (size_t)bf*(T_LEN*64) + n;    // t = 0
  out[a] = x[a];
}

// ---------------- launch ------------------------------------------------------
extern "C" void kernel_launch(void* const* d_in, const int* in_sizes, int n_in,
                              void* d_out, int out_size){
  const float* x    = (const float*)d_in[0];
  const float* Wqkv = (const float*)d_in[1];
  const float* bqkv = (const float*)d_in[2];
  const float* Wo   = (const float*)d_in[3];
  const float* bo   = (const float*)d_in[4];
  const float* Wfc  = (const float*)d_in[5];
  const float* bfc  = (const float*)d_in[6];
  float* out = (float*)d_out;

  k_transpose<<<(TB*EDIM + 255)/256, 256>>>(x);
  gemm_qkv<<<dim3(3*EDIM/128, TB/128), 256>>>(Wqkv, bqkv);
  k_attn<<<BATCH*NH, 256>>>();
  k_pctx<<<dim3(TM1, BATCH, NH), 128>>>();
  gemm_out<<<dim3(EDIM/128, ROWS2P/128), 256>>>(Wo, bo);
  k_head<<<dim3(TM1, BATCH), 256>>>(Wfc, bfc, out);
  k_copy0<<<(BATCH*64*64 + 255)/256, 256>>>(x, out);
}

// round 9
// speedup vs baseline: 2.5990x; 1.4221x over previous
#include <cuda_runtime.h>
#include <cuda_bf16.h>
#include <math.h>
#include <cstdint>

#define T_LEN 24
#define BATCH 16
#define NH    8
#define HDIM  512
#define EDIM  4096
#define TB    (T_LEN*BATCH)     /* 384  */
#define TM1   (T_LEN-1)         /* 23   */
#define ROWS2 (TM1*BATCH)       /* 368  */
#define GK    4096
#define KC    32
#define NCHUNK (GK/KC)          /* 128 */

// ---------------- scratch (static device globals; zero-init, no alloc) ------
// split layout: per 128-row block rb, per chunk c: 4096 words =
//   [hi plane 2048w][lo plane 2048w]; word = (row&127)*16 + pos(row,kk)
__device__ uint32_t g_Asp1[3u*NCHUNK*4096];    // xt split      (6.3 MB)
__device__ uint32_t g_Bsp1[96u*NCHUNK*4096];   // Wqkv split    (201 MB)
__device__ uint32_t g_Asp2[3u*NCHUNK*4096];    // pctx split    (6.3 MB) pad rows stay 0
__device__ uint32_t g_Bsp2[32u*NCHUNK*4096];   // Wo split      (67 MB)
__device__ float    g_qkv[TB*3*EDIM];
__device__ float    g_pooled[ROWS2*EDIM];
__device__ float    g_wbar[TM1*BATCH*NH*T_LEN];

// ---------------- layout helper (shared by writers and reader) ---------------
// kk = word-pair index within 32-wide chunk (0..15); s=k16 half, kb within half
// perm pairs (kb=tg, kb=tg+4) adjacently; half-swap swizzle by row bit1 fixes banks
__device__ __forceinline__ int posw(int row, int kk){
  int s = kk >> 3, kb = kk & 7;
  int perm = (kb < 4) ? (2*kb) : (2*(kb-4) + 1);
  return ((row & 127) * 16) + 8*(s ^ ((row >> 1) & 1)) + perm;
}

__device__ __forceinline__ uint32_t pack_hi(float x, float y, float& rx, float& ry){
  __nv_bfloat16 hx = __float2bfloat16(x), hy = __float2bfloat16(y);
  rx = x - __bfloat162float(hx);
  ry = y - __bfloat162float(hy);
  return ((uint32_t)__bfloat16_as_ushort(hy) << 16) | __bfloat16_as_ushort(hx);
}
__device__ __forceinline__ uint32_t pack_lo(float rx, float ry){
  __nv_bfloat16 lx = __float2bfloat16(rx), ly = __float2bfloat16(ry);
  return ((uint32_t)__bfloat16_as_ushort(ly) << 16) | __bfloat16_as_ushort(lx);
}

// ---------------- split kernels ----------------------------------------------
// generic weight split: W (nrows, 4096) row-major -> dst split planes
__global__ __launch_bounds__(256) void k_splitw(const float* __restrict__ W,
                                                uint32_t* __restrict__ dst, int nrows){
  int idx = blockIdx.x*256 + threadIdx.x;
  if (idx >= nrows*2048) return;
  int row = idx >> 11, kp = idx & 2047;
  int c = kp >> 4, kk = kp & 15;
  float2 v = *(const float2*)(W + (size_t)row*GK + 2*kp);
  float rx, ry;
  uint32_t hi = pack_hi(v.x, v.y, rx, ry);
  uint32_t lo = pack_lo(rx, ry);
  size_t base = ((size_t)((row >> 7)*NCHUNK + c))*4096 + posw(row, kk);
  dst[base] = hi; dst[base + 2048] = lo;
}

// x -> xt split (transpose fused): xt row = t*16+b, col e = f*64+n
__global__ __launch_bounds__(256) void k_splitx(const float* __restrict__ x){
  int idx = blockIdx.x*256 + threadIdx.x;
  if (idx >= TB*2048) return;
  int row = idx >> 11, kp = idx & 2047;
  int t = row >> 4, b = row & 15;
  int e = 2*kp, f = e >> 6, n = e & 63;
  const float* xp = x + (((size_t)(b*64 + f))*T_LEN + t)*64 + n;
  float2 v = { xp[0], xp[1] };
  float rx, ry;
  uint32_t hi = pack_hi(v.x, v.y, rx, ry);
  uint32_t lo = pack_lo(rx, ry);
  int c = kp >> 4, kk = kp & 15;
  size_t base = ((size_t)((row >> 7)*NCHUNK + c))*4096 + posw(row, kk);
  g_Asp1[base] = hi; g_Asp1[base + 2048] = lo;
}

// ---------------- cp.async helpers -------------------------------------------
__device__ __forceinline__ uint32_t smem_u32(const void* p){
  uint32_t a;
  asm("{ .reg .u64 t; cvta.to.shared.u64 t, %1; cvt.u32.u64 %0, t; }" : "=r"(a) : "l"(p));
  return a;
}
__device__ __forceinline__ void cpa16(uint32_t s, const void* g){
  asm volatile("cp.async.cg.shared.global [%0], [%1], 16;" :: "r"(s), "l"(g));
}
__device__ __forceinline__ void cpa_commit(){
  asm volatile("cp.async.commit_group;" ::: "memory");
}
__device__ __forceinline__ void cpa_wait2(){
  asm volatile("cp.async.wait_group 2;" ::: "memory");
}

// ---------------- mma.sync wrapper -------------------------------------------
__device__ __forceinline__ void mma16816(float* c,
                                         uint32_t a0, uint32_t a1, uint32_t a2, uint32_t a3,
                                         uint32_t b0, uint32_t b1){
  asm volatile(
    "mma.sync.aligned.m16n8k16.row.col.f32.bf16.bf16.f32 "
    "{%0,%1,%2,%3}, {%4,%5,%6,%7}, {%8,%9}, {%0,%1,%2,%3};"
    : "+f"(c[0]), "+f"(c[1]), "+f"(c[2]), "+f"(c[3])
    : "r"(a0), "r"(a1), "r"(a2), "r"(a3), "r"(b0), "r"(b1));
}

// ---------------- GEMM: C(M,Nn) = A @ B^T + bias (pre-split operands) --------
// stage bytes: [Ahi 8K][Alo 8K][Bhi 8K][Blo 8K] = 32KB, 4 stages = 128KB
#define STAGE_B 32768
#define GEMM_SMEM (4*STAGE_B)

__global__ __launch_bounds__(256,1) void gemm_tc(const uint32_t* __restrict__ Asp,
                                                 const uint32_t* __restrict__ Bsp,
                                                 const float* __restrict__ bias,
                                                 float* __restrict__ C,
                                                 int Nn, int Mvalid){
  extern __shared__ char smem[];
  const uint32_t sb = smem_u32(smem);
  const int tid = threadIdx.x, warp = tid >> 5, lane = tid & 31;
  const int g = lane >> 2, tg = lane & 3;
  const int wm = warp >> 2, wn = warp & 3;
  const int R0 = wm*64, N0 = wn*32;
  const int X = (g >> 1) & 1;                   // swizzle bit (row bit1 == g bit1)
  const uint4* Ag = (const uint4*)(Asp) + (size_t)blockIdx.y*NCHUNK*1024;
  const uint4* Bg = (const uint4*)(Bsp) + (size_t)blockIdx.x*NCHUNK*1024;

  float acc[4][4][4];
  #pragma unroll
  for (int i=0;i<4;i++)
    #pragma unroll
    for (int j=0;j<4;j++)
      #pragma unroll
      for (int r=0;r<4;r++) acc[i][j][r] = 0.f;

  // issue stage st <- chunk c (8 x 16B per thread)
  auto issue = [&](int st, int c){
    uint32_t dA = sb + st*STAGE_B + tid*16;
    uint32_t dB = dA + 16384;
    const uint4* a = Ag + (size_t)c*1024 + tid;
    const uint4* b = Bg + (size_t)c*1024 + tid;
    #pragma unroll
    for (int u=0;u<4;u++){
      cpa16(dA + u*4096, a + u*256);
      cpa16(dB + u*4096, b + u*256);
    }
  };

  issue(0,0); cpa_commit();
  issue(1,1); cpa_commit();
  issue(2,2); cpa_commit();

  const uint32_t pbs0 = (uint32_t)(8*(0^X) + 2*tg)*4;  // byte off within row seg, s=0
  const uint32_t pbs1 = (uint32_t)(8*(1^X) + 2*tg)*4;

  for (int c = 0; c < NCHUNK; c++){
    const int st = c & 3;
    cpa_wait2();
    __syncthreads();
    if (c+3 < NCHUNK) issue((c+3)&3, c+3);
    cpa_commit();

    const char* wb = smem + st*STAGE_B;
    #pragma unroll
    for (int s=0;s<2;s++){
      const uint32_t pb = s ? pbs1 : pbs0;
      uint2 bh[4], bl[4];
      #pragma unroll
      for (int j=0;j<4;j++){
        int n = N0 + 8*j + g;
        bh[j] = *(const uint2*)(wb + 16384 + n*64 + pb);
        bl[j] = *(const uint2*)(wb + 24576 + n*64 + pb);
      }
      #pragma unroll
      for (int i=0;i<4;i++){
        int r0 = R0 + 16*i + g;
        uint2 ah0 = *(const uint2*)(wb         + r0*64       + pb);
        uint2 ah1 = *(const uint2*)(wb         + r0*64 + 512 + pb);
        uint2 al0 = *(const uint2*)(wb + 8192  + r0*64       + pb);
        uint2 al1 = *(const uint2*)(wb + 8192  + r0*64 + 512 + pb);
        #pragma unroll
        for (int j=0;j<4;j++){
          mma16816(acc[i][j], ah0.x, ah1.x, ah0.y, ah1.y, bh[j].x, bh[j].y);
          mma16816(acc[i][j], ah0.x, ah1.x, ah0.y, ah1.y, bl[j].x, bl[j].y);
          mma16816(acc[i][j], al0.x, al1.x, al0.y, al1.y, bh[j].x, bh[j].y);
        }
      }
    }
    __syncthreads();
  }

  // epilogue
  const int bm = blockIdx.y*128, bn = blockIdx.x*128;
  #pragma unroll
  for (int i=0;i<4;i++){
    int row0 = bm + R0 + 16*i + g;
    int row1 = row0 + 8;
    #pragma unroll
    for (int j=0;j<4;j++){
      int col = bn + N0 + 8*j + 2*tg;
      float b0 = bias[col], b1 = bias[col+1];
      if (row0 < Mvalid){
        float2 o; o.x = acc[i][j][0] + b0; o.y = acc[i][j][1] + b1;
        *(float2*)&C[(size_t)row0*Nn + col] = o;
      }
      if (row1 < Mvalid){
        float2 o; o.x = acc[i][j][2] + b0; o.y = acc[i][j][3] + b1;
        *(float2*)&C[(size_t)row1*Nn + col] = o;
      }
    }
  }
}

// ---------------- small helpers ---------------------------------------------
__device__ __forceinline__ float wsum(float v){
  #pragma unroll
  for (int o=16;o;o>>=1) v += __shfl_xor_sync(0xffffffffu, v, o);
  return v;
}
__device__ __forceinline__ float wmax(float v){
  #pragma unroll
  for (int o=16;o;o>>=1) v = fmaxf(v, __shfl_xor_sync(0xffffffffu, v, o));
  return v;
}

// ---------------- attention: scores + per-step softmax + query-average -------
__global__ __launch_bounds__(256) void k_attn(){
  const int b = blockIdx.x >> 3, h = blockIdx.x & 7;
  __shared__ float Ks[T_LEN][257];
  __shared__ float base[T_LEN][T_LEN+1];
  const int tid = threadIdx.x, warp = tid>>5, lane = tid&31;

  for (int i=tid;i<T_LEN*T_LEN;i+=256) base[i/T_LEN][i%T_LEN] = 0.f;
  __syncthreads();

  for (int c=0;c<2;c++){
    for (int i=tid;i<T_LEN*256;i+=256){
      int k=i>>8, d=i&255;
      Ks[k][d] = g_qkv[((size_t)(k*BATCH+b))*(3*EDIM) + EDIM + h*HDIM + c*256 + d];
    }
    __syncthreads();
    for (int q=warp; q<T_LEN; q+=8){
      const float* qp = &g_qkv[((size_t)(q*BATCH+b))*(3*EDIM) + h*HDIM + c*256];
      float qr[8];
      #pragma unroll
      for (int i=0;i<8;i++) qr[i] = qp[lane + 32*i];
      for (int k=0;k<T_LEN;k++){
        float s = 0.f;
        #pragma unroll
        for (int i=0;i<8;i++) s += qr[i]*Ks[k][lane + 32*i];
        s = wsum(s);
        if (lane==0) base[q][k] += s;
      }
    }
    __syncthreads();
  }
  for (int i=tid;i<T_LEN*T_LEN;i+=256){
    int q=i/T_LEN, k=i%T_LEN;
    base[q][k] = base[q][k]*0.04419417382415922f + ((k<=q)?1.f:0.f);
  }
  __syncthreads();

  for (int t=warp; t<TM1; t+=8){
    const int k = lane;
    float acc = 0.f;
    for (int q=0; q<=t; q++){
      float bv = (k<=t) ? base[q][k] : -1e30f;
      float m  = wmax(bv);
      float e  = (k<=t) ? __expf(base[q][k]-m) : 0.f;
      float s  = wsum(e);
      acc += e / s;
    }
    if (k < T_LEN)
      g_wbar[(((t*BATCH)+b)*NH + h)*T_LEN + k] = acc / (float)(t+1);
  }
}

// ---------------- pooled context, split fused into epilogue ------------------
__global__ __launch_bounds__(128) void k_pctx(){
  const int t = blockIdx.x, b = blockIdx.y, h = blockIdx.z;
  __shared__ float w[T_LEN];
  const int tid = threadIdx.x;
  if (tid < T_LEN) w[tid] = (tid<=t) ? g_wbar[((t*BATCH+b)*NH+h)*T_LEN + tid] : 0.f;
  __syncthreads();
  float4 a = make_float4(0.f,0.f,0.f,0.f);
  for (int k=0;k<=t;k++){
    const float* vp = &g_qkv[((size_t)(k*BATCH+b))*(3*EDIM) + 2*EDIM + h*HDIM];
    float4 vv = *(const float4*)(vp + 4*tid);
    float wk = w[k];
    a.x += wk*vv.x; a.y += wk*vv.y; a.z += wk*vv.z; a.w += wk*vv.w;
  }
  // write split: row = t*16+b, cols h*512 + 4*tid .. +3
  const int row = t*BATCH + b;
  const int kp0 = h*256 + 2*tid;            // word-pair index (even)
  const int c   = kp0 >> 4;
  const int kk0 = kp0 & 15, kk1 = kk0 + 1;
  float rx, ry;
  uint32_t hi0 = pack_hi(a.x, a.y, rx, ry);
  uint32_t lo0 = pack_lo(rx, ry);
  uint32_t hi1 = pack_hi(a.z, a.w, rx, ry);
  uint32_t lo1 = pack_lo(rx, ry);
  size_t base = ((size_t)((row >> 7)*NCHUNK + c))*4096;
  int p0 = posw(row, kk0), p1 = posw(row, kk1);
  g_Asp2[base + p0] = hi0; g_Asp2[base + 2048 + p0] = lo0;
  g_Asp2[base + p1] = hi1; g_Asp2[base + 2048 + p1] = lo1;
}

// ---------------- head FC ----------------------------------------------------
__global__ __launch_bounds__(256) void k_head(const float* __restrict__ Wfc,
                                              const float* __restrict__ bfc,
                                              float* __restrict__ out){
  const int t = blockIdx.x, b = blockIdx.y;
  __shared__ float P[EDIM];
  __shared__ float Wf[64][65];
  const int tid = threadIdx.x;
  for (int i=tid;i<EDIM;i+=256) P[i] = g_pooled[((size_t)(t*BATCH+b))*EDIM + i];
  for (int i=tid;i<4096;i+=256) Wf[i>>6][i&63] = Wfc[i];
  __syncthreads();
  #pragma unroll 4
  for (int u=0;u<16;u++){
    int idx = tid + 256*u;
    int f = idx >> 6, n = idx & 63;
    float s = bfc[n];
    #pragma unroll
    for (int j=0;j<64;j++) s += P[f*64+j]*Wf[n][j];
    out[(((size_t)(b*64+f))*T_LEN + (t+1))*64 + n] = fmaxf(s, 0.f);
  }
}

// ---------------- copy t=0 slice ---------------------------------------------
__global__ void k_copy0(const float* __restrict__ x, float* __restrict__ out){
  int i = blockIdx.x*blockDim.x + threadIdx.x;
  if (i >= BATCH*64*64) return;
  int n = i & 63, bf = i >> 6;
  size_t a = (size_t)bf*(T_LEN*64) + n;    // t = 0
  out[a] = x[a];
}

// ---------------- launch ------------------------------------------------------
extern "C" void kernel_launch(void* const* d_in, const int* in_sizes, int n_in,
                              void* d_out, int out_size){
  const float* x    = (const float*)d_in[0];
  const float* Wqkv = (const float*)d_in[1];
  const float* bqkv = (const float*)d_in[2];
  const float* Wo   = (const float*)d_in[3];
  const float* bo   = (const float*)d_in[4];
  const float* Wfc  = (const float*)d_in[5];
  const float* bfc  = (const float*)d_in[6];
  float* out = (float*)d_out;

  cudaFuncSetAttribute(gemm_tc, cudaFuncAttributeMaxDynamicSharedMemorySize, GEMM_SMEM);

  uint32_t *Asp1, *Bsp1, *Asp2, *Bsp2;
  float *qkv, *pooled;
  cudaGetSymbolAddress((void**)&Asp1, g_Asp1);
  cudaGetSymbolAddress((void**)&Bsp1, g_Bsp1);
  cudaGetSymbolAddress((void**)&Asp2, g_Asp2);
  cudaGetSymbolAddress((void**)&Bsp2, g_Bsp2);
  cudaGetSymbolAddress((void**)&qkv,    g_qkv);
  cudaGetSymbolAddress((void**)&pooled, g_pooled);

  k_splitx<<<(TB*2048 + 255)/256, 256>>>(x);
  k_splitw<<<(12288*2048 + 255)/256, 256>>>(Wqkv, Bsp1, 12288);
  gemm_tc<<<dim3(96, 3), 256, GEMM_SMEM>>>(Asp1, Bsp1, bqkv, qkv, 3*EDIM, TB);
  k_attn<<<BATCH*NH, 256>>>();
  k_pctx<<<dim3(TM1, BATCH, NH), 128>>>();
  k_splitw<<<(4096*2048 + 255)/256, 256>>>(Wo, Bsp2, 4096);
  gemm_tc<<<dim3(32, 3), 256, GEMM_SMEM>>>(Asp2, Bsp2, bo, pooled, EDIM, ROWS2);
  k_head<<<dim3(TM1, BATCH), 256>>>(Wfc, bfc, out);
  k_copy0<<<(BATCH*64*64 + 255)/256, 256>>>(x, out);
}

// round 10
// speedup vs baseline: 2.6778x; 1.0303x over previous
#include <cuda_runtime.h>
#include <cuda_bf16.h>
#include <math.h>
#include <cstdint>

#define T_LEN 24
#define BATCH 16
#define NH    8
#define HDIM  512
#define EDIM  4096
#define TB    (T_LEN*BATCH)     /* 384  */
#define TM1   (T_LEN-1)         /* 23   */
#define ROWS2 (TM1*BATCH)       /* 368  */
#define GK    4096
#define KC    32
#define NCHUNK (GK/KC)          /* 128 */

// ---------------- scratch (static device globals; zero-init, no alloc) ------
__device__ uint32_t g_Asp1[3u*NCHUNK*4096];    // xt split      (6.3 MB)
__device__ uint32_t g_Bsp1[96u*NCHUNK*4096];   // Wqkv split    (201 MB)
__device__ uint32_t g_Asp2[3u*NCHUNK*4096];    // pctx split    (6.3 MB) pad rows stay 0
__device__ uint32_t g_Bsp2[32u*NCHUNK*4096];   // Wo split      (67 MB)
__device__ float    g_qkv[TB*3*EDIM];
__device__ float    g_pooled[ROWS2*EDIM];
__device__ float    g_wbar[TM1*BATCH*NH*T_LEN];

// ---------------- layout helper (shared by writers and reader) ---------------
__device__ __forceinline__ int posw(int row, int kk){
  int s = kk >> 3, kb = kk & 7;
  int perm = (kb < 4) ? (2*kb) : (2*(kb-4) + 1);
  return ((row & 127) * 16) + 8*(s ^ ((row >> 1) & 1)) + perm;
}

__device__ __forceinline__ uint32_t pack_hi(float x, float y, float& rx, float& ry){
  __nv_bfloat16 hx = __float2bfloat16(x), hy = __float2bfloat16(y);
  rx = x - __bfloat162float(hx);
  ry = y - __bfloat162float(hy);
  return ((uint32_t)__bfloat16_as_ushort(hy) << 16) | __bfloat16_as_ushort(hx);
}
__device__ __forceinline__ uint32_t pack_lo(float rx, float ry){
  __nv_bfloat16 lx = __float2bfloat16(rx), ly = __float2bfloat16(ry);
  return ((uint32_t)__bfloat16_as_ushort(ly) << 16) | __bfloat16_as_ushort(lx);
}

// ---------------- split kernels ----------------------------------------------
__global__ __launch_bounds__(256) void k_splitw(const float* __restrict__ W,
                                                uint32_t* __restrict__ dst, int nrows){
  int idx = blockIdx.x*256 + threadIdx.x;
  if (idx >= nrows*2048) return;
  int row = idx >> 11, kp = idx & 2047;
  int c = kp >> 4, kk = kp & 15;
  float2 v = *(const float2*)(W + (size_t)row*GK + 2*kp);
  float rx, ry;
  uint32_t hi = pack_hi(v.x, v.y, rx, ry);
  uint32_t lo = pack_lo(rx, ry);
  size_t base = ((size_t)((row >> 7)*NCHUNK + c))*4096 + posw(row, kk);
  dst[base] = hi; dst[base + 2048] = lo;
}

__global__ __launch_bounds__(256) void k_splitx(const float* __restrict__ x){
  int idx = blockIdx.x*256 + threadIdx.x;
  if (idx >= TB*2048) return;
  int row = idx >> 11, kp = idx & 2047;
  int t = row >> 4, b = row & 15;
  int e = 2*kp, f = e >> 6, n = e & 63;
  const float* xp = x + (((size_t)(b*64 + f))*T_LEN + t)*64 + n;
  float2 v = { xp[0], xp[1] };
  float rx, ry;
  uint32_t hi = pack_hi(v.x, v.y, rx, ry);
  uint32_t lo = pack_lo(rx, ry);
  int c = kp >> 4, kk = kp & 15;
  size_t base = ((size_t)((row >> 7)*NCHUNK + c))*4096 + posw(row, kk);
  g_Asp1[base] = hi; g_Asp1[base + 2048] = lo;
}

// ---------------- cp.async helpers -------------------------------------------
__device__ __forceinline__ uint32_t smem_u32(const void* p){
  uint32_t a;
  asm("{ .reg .u64 t; cvta.to.shared.u64 t, %1; cvt.u32.u64 %0, t; }" : "=r"(a) : "l"(p));
  return a;
}
__device__ __forceinline__ void cpa16(uint32_t s, const void* g){
  asm volatile("cp.async.cg.shared.global [%0], [%1], 16;" :: "r"(s), "l"(g));
}
__device__ __forceinline__ void cpa_commit(){
  asm volatile("cp.async.commit_group;" ::: "memory");
}
__device__ __forceinline__ void cpa_wait2(){
  asm volatile("cp.async.wait_group 2;" ::: "memory");
}

// ---------------- mma.sync wrapper -------------------------------------------
__device__ __forceinline__ void mma16816(float* c,
                                         uint32_t a0, uint32_t a1, uint32_t a2, uint32_t a3,
                                         uint32_t b0, uint32_t b1){
  asm volatile(
    "mma.sync.aligned.m16n8k16.row.col.f32.bf16.bf16.f32 "
    "{%0,%1,%2,%3}, {%4,%5,%6,%7}, {%8,%9}, {%0,%1,%2,%3};"
    : "+f"(c[0]), "+f"(c[1]), "+f"(c[2]), "+f"(c[3])
    : "r"(a0), "r"(a1), "r"(a2), "r"(a3), "r"(b0), "r"(b1));
}

// ---------------- GEMM: C(M,Nn) = A @ B^T + bias (pre-split operands) --------
#define STAGE_B 32768
#define GEMM_SMEM (4*STAGE_B)

__global__ __launch_bounds__(256,1) void gemm_tc(const uint32_t* __restrict__ Asp,
                                                 const uint32_t* __restrict__ Bsp,
                                                 const float* __restrict__ bias,
                                                 float* __restrict__ C,
                                                 int Nn, int Mvalid){
  extern __shared__ char smem[];
  const uint32_t sb = smem_u32(smem);
  const int tid = threadIdx.x, warp = tid >> 5, lane = tid & 31;
  const int g = lane >> 2, tg = lane & 3;
  const int wm = warp >> 2, wn = warp & 3;
  const int R0 = wm*64, N0 = wn*32;
  const int X = (g >> 1) & 1;
  const uint4* Ag = (const uint4*)(Asp) + (size_t)blockIdx.y*NCHUNK*1024;
  const uint4* Bg = (const uint4*)(Bsp) + (size_t)blockIdx.x*NCHUNK*1024;

  float acc[4][4][4];
  #pragma unroll
  for (int i=0;i<4;i++)
    #pragma unroll
    for (int j=0;j<4;j++)
      #pragma unroll
      for (int r=0;r<4;r++) acc[i][j][r] = 0.f;

  auto issue = [&](int st, int c){
    uint32_t dA = sb + st*STAGE_B + tid*16;
    uint32_t dB = dA + 16384;
    const uint4* a = Ag + (size_t)c*1024 + tid;
    const uint4* b = Bg + (size_t)c*1024 + tid;
    #pragma unroll
    for (int u=0;u<4;u++){
      cpa16(dA + u*4096, a + u*256);
      cpa16(dB + u*4096, b + u*256);
    }
  };

  issue(0,0); cpa_commit();
  issue(1,1); cpa_commit();
  issue(2,2); cpa_commit();

  const uint32_t pbs0 = (uint32_t)(8*(0^X) + 2*tg)*4;
  const uint32_t pbs1 = (uint32_t)(8*(1^X) + 2*tg)*4;

  for (int c = 0; c < NCHUNK; c++){
    const int st = c & 3;
    cpa_wait2();
    __syncthreads();                 // single barrier per chunk: after this, all
                                     // warps are done with stage (c-1)&3
    if (c+3 < NCHUNK) issue((c+3)&3, c+3);
    cpa_commit();

    const char* wb = smem + st*STAGE_B;
    #pragma unroll
    for (int s=0;s<2;s++){
      const uint32_t pb = s ? pbs1 : pbs0;
      uint2 bh[4], bl[4];
      #pragma unroll
      for (int j=0;j<4;j++){
        int n = N0 + 8*j + g;
        bh[j] = *(const uint2*)(wb + 16384 + n*64 + pb);
        bl[j] = *(const uint2*)(wb + 24576 + n*64 + pb);
      }
      #pragma unroll
      for (int i=0;i<4;i++){
        int r0 = R0 + 16*i + g;
        uint2 ah0 = *(const uint2*)(wb         + r0*64       + pb);
        uint2 ah1 = *(const uint2*)(wb         + r0*64 + 512 + pb);
        uint2 al0 = *(const uint2*)(wb + 8192  + r0*64       + pb);
        uint2 al1 = *(const uint2*)(wb + 8192  + r0*64 + 512 + pb);
        #pragma unroll
        for (int j=0;j<4;j++){
          mma16816(acc[i][j], ah0.x, ah1.x, ah0.y, ah1.y, bh[j].x, bh[j].y);
          mma16816(acc[i][j], ah0.x, ah1.x, ah0.y, ah1.y, bl[j].x, bl[j].y);
          mma16816(acc[i][j], al0.x, al1.x, al0.y, al1.y, bh[j].x, bh[j].y);
        }
      }
    }
  }

  const int bm = blockIdx.y*128, bn = blockIdx.x*128;
  #pragma unroll
  for (int i=0;i<4;i++){
    int row0 = bm + R0 + 16*i + g;
    int row1 = row0 + 8;
    #pragma unroll
    for (int j=0;j<4;j++){
      int col = bn + N0 + 8*j + 2*tg;
      float b0 = bias[col], b1 = bias[col+1];
      if (row0 < Mvalid){
        float2 o; o.x = acc[i][j][0] + b0; o.y = acc[i][j][1] + b1;
        *(float2*)&C[(size_t)row0*Nn + col] = o;
      }
      if (row1 < Mvalid){
        float2 o; o.x = acc[i][j][2] + b0; o.y = acc[i][j][3] + b1;
        *(float2*)&C[(size_t)row1*Nn + col] = o;
      }
    }
  }
}

// ---------------- small helpers ---------------------------------------------
__device__ __forceinline__ float wsum(float v){
  #pragma unroll
  for (int o=16;o;o>>=1) v += __shfl_xor_sync(0xffffffffu, v, o);
  return v;
}

// ---------------- attention --------------------------------------------------
// E[q][k] = exp(score*scale + tril); S[q][t] via inclusive lane-scan;
// wbar[t][k] = (1/(t+1)) * sum_{q<=t} E[q][k] / S[q][t]
__global__ __launch_bounds__(256) void k_attn(){
  const int b = blockIdx.x >> 3, h = blockIdx.x & 7;
  __shared__ float Ks[T_LEN][257];
  __shared__ float E[T_LEN][T_LEN+1];
  __shared__ float R[T_LEN][T_LEN+1];
  const int tid = threadIdx.x, warp = tid>>5, lane = tid&31;

  for (int i=tid;i<T_LEN*T_LEN;i+=256) E[i/T_LEN][i%T_LEN] = 0.f;
  __syncthreads();

  for (int c=0;c<2;c++){
    for (int i=tid;i<T_LEN*256;i+=256){
      int k=i>>8, d=i&255;
      Ks[k][d] = g_qkv[((size_t)(k*BATCH+b))*(3*EDIM) + EDIM + h*HDIM + c*256 + d];
    }
    __syncthreads();
    for (int q=warp; q<T_LEN; q+=8){
      const float* qp = &g_qkv[((size_t)(q*BATCH+b))*(3*EDIM) + h*HDIM + c*256];
      float qr[8];
      #pragma unroll
      for (int i=0;i<8;i++) qr[i] = qp[lane + 32*i];
      #pragma unroll 4
      for (int k=0;k<T_LEN;k++){
        float s = 0.f;
        #pragma unroll
        for (int i=0;i<8;i++) s += qr[i]*Ks[k][lane + 32*i];
        s = wsum(s);
        if (lane==0) E[q][k] += s;
      }
    }
    __syncthreads();
  }

  // exp + inclusive prefix scan per row (warp per row)
  for (int q=warp; q<T_LEN; q+=8){
    float e = 0.f;
    if (lane < T_LEN){
      float bse = E[q][lane]*0.04419417382415922f + ((lane<=q)?1.f:0.f);
      e = __expf(bse);
      E[q][lane] = e;
    }
    float sc = e;
    #pragma unroll
    for (int o=1;o<32;o<<=1){
      float v = __shfl_up_sync(0xffffffffu, sc, o);
      if (lane >= o) sc += v;
    }
    if (lane < T_LEN) R[q][lane] = 1.f / sc;
  }
  __syncthreads();

  // wbar accumulation: warp per t, lane per k
  for (int t=warp; t<TM1; t+=8){
    if (lane <= t){
      float acc = 0.f;
      #pragma unroll 4
      for (int q=0; q<=t; q++) acc += E[q][lane]*R[q][t];
      g_wbar[(((t*BATCH)+b)*NH + h)*T_LEN + lane] = acc / (float)(t+1);
    }
  }
}

// ---------------- pooled context, split fused into epilogue ------------------
__global__ __launch_bounds__(128) void k_pctx(){
  const int t = blockIdx.x, b = blockIdx.y, h = blockIdx.z;
  __shared__ float w[T_LEN];
  const int tid = threadIdx.x;
  if (tid < T_LEN) w[tid] = (tid<=t) ? g_wbar[((t*BATCH+b)*NH+h)*T_LEN + tid] : 0.f;
  __syncthreads();
  float4 a = make_float4(0.f,0.f,0.f,0.f);
  for (int k=0;k<=t;k++){
    const float* vp = &g_qkv[((size_t)(k*BATCH+b))*(3*EDIM) + 2*EDIM + h*HDIM];
    float4 vv = *(const float4*)(vp + 4*tid);
    float wk = w[k];
    a.x += wk*vv.x; a.y += wk*vv.y; a.z += wk*vv.z; a.w += wk*vv.w;
  }
  const int row = t*BATCH + b;
  const int kp0 = h*256 + 2*tid;
  const int c   = kp0 >> 4;
  const int kk0 = kp0 & 15, kk1 = kk0 + 1;
  float rx, ry;
  uint32_t hi0 = pack_hi(a.x, a.y, rx, ry);
  uint32_t lo0 = pack_lo(rx, ry);
  uint32_t hi1 = pack_hi(a.z, a.w, rx, ry);
  uint32_t lo1 = pack_lo(rx, ry);
  size_t base = ((size_t)((row >> 7)*NCHUNK + c))*4096;
  int p0 = posw(row, kk0), p1 = posw(row, kk1);
  g_Asp2[base + p0] = hi0; g_Asp2[base + 2048 + p0] = lo0;
  g_Asp2[base + p1] = hi1; g_Asp2[base + 2048 + p1] = lo1;
}

// ---------------- head FC ----------------------------------------------------
__global__ __launch_bounds__(256) void k_head(const float* __restrict__ Wfc,
                                              const float* __restrict__ bfc,
                                              float* __restrict__ out){
  const int t = blockIdx.x, b = blockIdx.y;
  __shared__ float P[EDIM];
  __shared__ float Wf[64][65];
  const int tid = threadIdx.x;
  for (int i=tid;i<EDIM;i+=256) P[i] = g_pooled[((size_t)(t*BATCH+b))*EDIM + i];
  for (int i=tid;i<4096;i+=256) Wf[i>>6][i&63] = Wfc[i];
  __syncthreads();
  #pragma unroll 4
  for (int u=0;u<16;u++){
    int idx = tid + 256*u;
    int f = idx >> 6, n = idx & 63;
    float s = bfc[n];
    #pragma unroll
    for (int j=0;j<64;j++) s += P[f*64+j]*Wf[n][j];
    out[(((size_t)(b*64+f))*T_LEN + (t+1))*64 + n] = fmaxf(s, 0.f);
  }
}

// ---------------- copy t=0 slice ---------------------------------------------
__global__ void k_copy0(const float* __restrict__ x, float* __restrict__ out){
  int i = blockIdx.x*blockDim.x + threadIdx.x;
  if (i >= BATCH*64*64) return;
  int n = i & 63, bf = i >> 6;
  size_t a = (size_t)bf*(T_LEN*64) + n;    // t = 0
  out[a] = x[a];
}

// ---------------- launch ------------------------------------------------------
extern "C" void kernel_launch(void* const* d_in, const int* in_sizes, int n_in,
                              void* d_out, int out_size){
  const float* x    = (const float*)d_in[0];
  const float* Wqkv = (const float*)d_in[1];
  const float* bqkv = (const float*)d_in[2];
  const float* Wo   = (const float*)d_in[3];
  const float* bo   = (const float*)d_in[4];
  const float* Wfc  = (const float*)d_in[5];
  const float* bfc  = (const float*)d_in[6];
  float* out = (float*)d_out;

  cudaFuncSetAttribute(gemm_tc, cudaFuncAttributeMaxDynamicSharedMemorySize, GEMM_SMEM);

  uint32_t *Asp1, *Bsp1, *Asp2, *Bsp2;
  float *qkv, *pooled;
  cudaGetSymbolAddress((void**)&Asp1, g_Asp1);
  cudaGetSymbolAddress((void**)&Bsp1, g_Bsp1);
  cudaGetSymbolAddress((void**)&Asp2, g_Asp2);
  cudaGetSymbolAddress((void**)&Bsp2, g_Bsp2);
  cudaGetSymbolAddress((void**)&qkv,    g_qkv);
  cudaGetSymbolAddress((void**)&pooled, g_pooled);

  // launch order chosen so gemm_tc (qkv) sits at profiled slot (index 3)
  k_splitx<<<(TB*2048 + 255)/256, 256>>>(x);                       // 0
  k_splitw<<<(12288*2048 + 255)/256, 256>>>(Wqkv, Bsp1, 12288);    // 1
  k_splitw<<<(4096*2048 + 255)/256, 256>>>(Wo, Bsp2, 4096);        // 2
  gemm_tc<<<dim3(96, 3), 256, GEMM_SMEM>>>(Asp1, Bsp1, bqkv, qkv, 3*EDIM, TB);   // 3
  k_attn<<<BATCH*NH, 256>>>();                                     // 4
  k_pctx<<<dim3(TM1, BATCH, NH), 128>>>();                         // 5
  gemm_tc<<<dim3(32, 3), 256, GEMM_SMEM>>>(Asp2, Bsp2, bo, pooled, EDIM, ROWS2); // 6
  k_head<<<dim3(TM1, BATCH), 256>>>(Wfc, bfc, out);                // 7
  k_copy0<<<(BATCH*64*64 + 255)/256, 256>>>(x, out);               // 8
}